// round 15
// baseline (speedup 1.0000x reference)
#include <cuda_runtime.h>
#include <cuda_fp16.h>
#include <stdint.h>
#include <math.h>

// ---------------------------------------------------------------------------
// Problem constants
// ---------------------------------------------------------------------------
#define BB 4
#define SS 4096
#define DD 512
#define M_TOTAL (BB * SS)   // 16384
#define INV_SQRT_D 0.04419417382415922f

// ---------------------------------------------------------------------------
// Scratch (__device__ globals; allocation-free rule)
// ---------------------------------------------------------------------------
__device__ __align__(256) __half g_xh[(size_t)M_TOTAL * DD];
__device__ __align__(256) __half g_Wh[(size_t)3 * DD * DD];
__device__ __align__(256) __half g_bh[(size_t)SS * SS];          // bias fp16
__device__ __align__(256) __half g_Qh[(size_t)M_TOTAL * DD];     // pre-scaled by 1/sqrt(D)
__device__ __align__(256) __half g_Kh[(size_t)M_TOTAL * DD];
__device__ __align__(256) __half g_Vt[(size_t)BB * DD * SS];     // V^T [b][d][s]
__device__ __align__(256) __half g_P [(size_t)BB * SS * SS];     // sigmoid weights

// ---------------------------------------------------------------------------
// Helpers
// ---------------------------------------------------------------------------
__device__ __forceinline__ uint32_t smem_u32(const void* p) {
    uint32_t a;
    asm("{ .reg .u64 t; cvta.to.shared.u64 t, %1; cvt.u32.u64 %0, t; }" : "=r"(a) : "l"(p));
    return a;
}

#define CP_ASYNC16(dst, src) \
    asm volatile("cp.async.cg.shared.global [%0], [%1], 16;" :: "r"(dst), "l"(src))
#define CP_COMMIT() asm volatile("cp.async.commit_group;")
#define CP_WAIT1()  asm volatile("cp.async.wait_group 1;" ::: "memory")
#define CP_WAIT0()  asm volatile("cp.async.wait_group 0;" ::: "memory")

__device__ __forceinline__ void ldsm4(uint32_t (&r)[4], uint32_t addr) {
    asm volatile("ldmatrix.sync.aligned.m8n8.x4.shared.b16 {%0,%1,%2,%3}, [%4];"
                 : "=r"(r[0]), "=r"(r[1]), "=r"(r[2]), "=r"(r[3]) : "r"(addr));
}

__device__ __forceinline__ void mma16816h(float (&d)[4], const uint32_t (&a)[4],
                                          uint32_t b0, uint32_t b1) {
    asm volatile(
        "mma.sync.aligned.m16n8k16.row.col.f32.f16.f16.f32 "
        "{%0,%1,%2,%3}, {%4,%5,%6,%7}, {%8,%9}, {%0,%1,%2,%3};"
        : "+f"(d[0]), "+f"(d[1]), "+f"(d[2]), "+f"(d[3])
        : "r"(a[0]), "r"(a[1]), "r"(a[2]), "r"(a[3]), "r"(b0), "r"(b1));
}

__device__ __forceinline__ uint32_t pack_h2(float a, float b) {
    __half2 h = __floats2half2_rn(a, b);
    return *(uint32_t*)&h;
}

// sigmoid(x) = 0.5*tanh(0.5x) + 0.5 — one MUFU op + one FMA.
__device__ __forceinline__ float fast_sigmoid(float x) {
    float t;
    asm("tanh.approx.f32 %0, %1;" : "=f"(t) : "f"(x * 0.5f));
    return fmaf(0.5f, t, 0.5f);
}

// ===========================================================================
// Unified fp16 GEMM core: 128 threads = 4 warps (2M x 2N of 64x64 warp
// tiles), CTA tile 128(M) x 128(N), BK=64, 3-stage cp.async (32KB/stage,
// 96KB total) -> 2 CTAs/SM.
// NT GEMM: A[M,K] row-major fp16, B[N,K] row-major fp16.
// 128B rows, XOR swizzle: chunk ^= (row & 7).
// ===========================================================================
#define NCT 128
#define STAGE_BYTES 32768
#define SMEM_GEMM (3 * STAGE_BYTES)    // 96 KB

__device__ __forceinline__ void load_stage(
    uint32_t sb, const __half* A, int lda, const __half* B, int ldb, int k0, int tid)
{
#pragma unroll
    for (int it = 0; it < 8; ++it) {     // A: 128 rows * 8 chunks = 1024
        int u = it * NCT + tid;
        int row = u >> 3;
        int ch = u & 7;
        uint32_t soff = (uint32_t)row * 128 + ((uint32_t)(ch ^ (row & 7)) << 4);
        CP_ASYNC16(sb + soff, (const char*)(A + (size_t)row * lda + k0) + ch * 16);
    }
#pragma unroll
    for (int it = 0; it < 8; ++it) {     // B: 128 rows * 8 chunks = 1024
        int u = it * NCT + tid;
        int row = u >> 3;
        int ch = u & 7;
        uint32_t soff = (uint32_t)row * 128 + ((uint32_t)(ch ^ (row & 7)) << 4);
        CP_ASYNC16(sb + 16384 + soff, (const char*)(B + (size_t)row * ldb + k0) + ch * 16);
    }
}

template<int KTILES>
__device__ __forceinline__ void gemm_core(
    const __half* __restrict__ A, int lda,
    const __half* __restrict__ B, int ldb,
    uint32_t sbase, float (&acc)[32][4])
{
    const int tid  = threadIdx.x;
    const int lane = tid & 31;
    const int wid  = tid >> 5;
    const int warpM = wid & 1;    // 0..1 -> 64 rows each
    const int warpN = wid >> 1;   // 0..1 -> 64 cols each

#pragma unroll
    for (int i = 0; i < 32; ++i)
#pragma unroll
        for (int j = 0; j < 4; ++j) acc[i][j] = 0.0f;

    load_stage(sbase, A, lda, B, ldb, 0, tid);
    CP_COMMIT();
    if (KTILES > 1) {
        load_stage(sbase + STAGE_BYTES, A, lda, B, ldb, 64, tid);
        CP_COMMIT();
    }

    const int arow_base = warpM * 64 + (lane & 15);
    const int a_kh = lane >> 4;
    const int brow = warpN * 64 + ((lane >> 4) << 3) + (lane & 7);
    const int b_kh = (lane >> 3) & 1;

#pragma unroll 1
    for (int kt = 0; kt < KTILES; ++kt) {
        if (kt + 1 < KTILES) { CP_WAIT1(); } else { CP_WAIT0(); }
        __syncthreads();
        if (kt + 2 < KTILES) {
            load_stage(sbase + (uint32_t)((kt + 2) % 3) * STAGE_BYTES,
                       A, lda, B, ldb, (kt + 2) * 64, tid);
            CP_COMMIT();
        }

        uint32_t sb = sbase + (uint32_t)(kt % 3) * STAGE_BYTES;
#pragma unroll
        for (int ks = 0; ks < 4; ++ks) {
            uint32_t a[4][4], b[4][4];
#pragma unroll
            for (int mt = 0; mt < 4; ++mt) {
                int r = arow_base + mt * 16;
                uint32_t ch = (uint32_t)(ks * 2 + a_kh) ^ (uint32_t)(r & 7);
                ldsm4(a[mt], sb + (uint32_t)r * 128 + ch * 16);
            }
#pragma unroll
            for (int nb = 0; nb < 4; ++nb) {
                int r = brow + nb * 16;
                uint32_t ch = (uint32_t)(ks * 2 + b_kh) ^ (uint32_t)(r & 7);
                ldsm4(b[nb], sb + 16384 + (uint32_t)r * 128 + ch * 16);
            }
#pragma unroll
            for (int mt = 0; mt < 4; ++mt)
#pragma unroll
                for (int nt = 0; nt < 8; ++nt)
                    mma16816h(acc[mt * 8 + nt], a[mt],
                              b[nt >> 1][(nt & 1) * 2], b[nt >> 1][(nt & 1) * 2 + 1]);
        }
    }
}

// ---------------------------------------------------------------------------
// Merged convert: x, Wq/Wk/Wv, and bias fp32 -> fp16, one launch.
// ---------------------------------------------------------------------------
#define NX4 (M_TOTAL * DD / 4)
#define NW4 (DD * DD / 4)
#define NB4 (SS * SS / 4)

__global__ void __launch_bounds__(256)
cvt_all(const float* __restrict__ x,
        const float* __restrict__ Wq, const float* __restrict__ Wk,
        const float* __restrict__ Wv, const float* __restrict__ bias)
{
    int i = blockIdx.x * 256 + threadIdx.x;
    const float* src;
    __half* dst;
    int j;
    if (i < NX4) {
        src = x; dst = g_xh; j = i;
    } else if (i < NX4 + 3 * NW4) {
        int w = i - NX4;
        int z = w / NW4;
        j = w - z * NW4;
        src = (z == 0) ? Wq : ((z == 1) ? Wk : Wv);
        dst = g_Wh + (size_t)z * DD * DD;
    } else {
        int v = i - (NX4 + 3 * NW4);
        if (v >= NB4) return;
        src = bias; dst = g_bh; j = v;
    }
    float4 v = *(const float4*)(src + (size_t)j * 4);
    *(uint2*)(dst + (size_t)j * 4) = make_uint2(pack_h2(v.x, v.y), pack_h2(v.z, v.w));
}

// ---------------------------------------------------------------------------
// QKV projection: C = x @ W^T + b, grid.z selects (Q,K,V). 2 CTAs/SM.
// z==2 (V) epilogue transposes the tile in smem and writes g_Vt directly.
// ---------------------------------------------------------------------------
#define TP 130   // transpose smem pitch in halves

__global__ void __launch_bounds__(NCT, 2)
qkv_mma(const float* __restrict__ bq, const float* __restrict__ bk,
        const float* __restrict__ bv)
{
    extern __shared__ char smem[];
    uint32_t sbase = smem_u32(smem);
    const int z = blockIdx.z;
    const int mrow = blockIdx.y * 128;
    const int ncol = blockIdx.x * 128;
    const int tid = threadIdx.x;

    const __half* A = g_xh + (size_t)mrow * DD;
    const __half* B = g_Wh + (size_t)z * DD * DD + (size_t)ncol * DD;

    float acc[32][4];
    gemm_core<DD / 64>(A, DD, B, DD, sbase, acc);

    const float* bvec = (z == 0) ? bq : ((z == 1) ? bk : bv);
    const int lane = tid & 31, wid = tid >> 5;
    const int warpM = wid & 1, warpN = wid >> 1;

    if (z != 2) {
#pragma unroll
        for (int mt = 0; mt < 4; ++mt)
#pragma unroll
            for (int nt = 0; nt < 8; ++nt)
#pragma unroll
                for (int h = 0; h < 2; ++h) {
                    int r = mrow + warpM * 64 + mt * 16 + (lane >> 2) + h * 8;
                    int c = ncol + warpN * 64 + nt * 8 + (lane & 3) * 2;
                    float v0 = acc[mt * 8 + nt][h * 2 + 0] + bvec[c];
                    float v1 = acc[mt * 8 + nt][h * 2 + 1] + bvec[c + 1];
                    size_t o = (size_t)r * DD + c;
                    if (z == 0) {
                        *(uint32_t*)(g_Qh + o) = pack_h2(v0 * INV_SQRT_D, v1 * INV_SQRT_D);
                    } else {
                        *(uint32_t*)(g_Kh + o) = pack_h2(v0, v1);
                    }
                }
    } else {
        // V: transpose tile in smem (reuse pipeline stages), write g_Vt rows.
        __syncthreads();
        __half* tsm = (__half*)smem;
#pragma unroll
        for (int mt = 0; mt < 4; ++mt)
#pragma unroll
            for (int nt = 0; nt < 8; ++nt)
#pragma unroll
                for (int h = 0; h < 2; ++h) {
                    int rl = warpM * 64 + mt * 16 + (lane >> 2) + h * 8;   // s-local
                    int cl = warpN * 64 + nt * 8 + (lane & 3) * 2;        // d-local
                    float v0 = acc[mt * 8 + nt][h * 2 + 0] + bvec[ncol + cl];
                    float v1 = acc[mt * 8 + nt][h * 2 + 1] + bvec[ncol + cl + 1];
                    tsm[(cl)     * TP + rl] = __float2half_rn(v0);
                    tsm[(cl + 1) * TP + rl] = __float2half_rn(v1);
                }
        __syncthreads();

        const int bz = mrow / SS;
        const int s0 = mrow % SS;
        const __half* src = tsm + (size_t)tid * TP;
        __half* dst = g_Vt + ((size_t)bz * DD + (ncol + tid)) * SS + s0;
#pragma unroll
        for (int i = 0; i < 16; ++i) {
            uint32_t u0 = *(const uint32_t*)(src + i * 8 + 0);
            uint32_t u1 = *(const uint32_t*)(src + i * 8 + 2);
            uint32_t u2 = *(const uint32_t*)(src + i * 8 + 4);
            uint32_t u3 = *(const uint32_t*)(src + i * 8 + 6);
            *(uint4*)(dst + i * 8) = make_uint4(u0, u1, u2, u3);
        }
    }
}

// ---------------------------------------------------------------------------
// Scores: P = sigmoid(Q K^T + bias), Q pre-scaled, fp16 bias. fp16 out.
// 2 CTAs/SM. grid.x = (ncol_tiles) * (b), b fastest -> bias L2-shared.
// ---------------------------------------------------------------------------
__global__ void __launch_bounds__(NCT, 2)
scores_mma()
{
    extern __shared__ char smem[];
    uint32_t sbase = smem_u32(smem);
    const int bz = blockIdx.x & 3;
    const int ncol = (blockIdx.x >> 2) * 128;
    const int mrow = blockIdx.y * 128;

    const __half* A = g_Qh + ((size_t)bz * SS + mrow) * DD;
    const __half* B = g_Kh + ((size_t)bz * SS + ncol) * DD;

    float acc[32][4];
    gemm_core<DD / 64>(A, DD, B, DD, sbase, acc);

    const int lane = threadIdx.x & 31, wid = threadIdx.x >> 5;
    const int warpM = wid & 1, warpN = wid >> 1;

#pragma unroll
    for (int mt = 0; mt < 4; ++mt)
#pragma unroll
        for (int nt = 0; nt < 8; ++nt)
#pragma unroll
            for (int h = 0; h < 2; ++h) {
                int r = mrow + warpM * 64 + mt * 16 + (lane >> 2) + h * 8;
                int c = ncol + warpN * 64 + nt * 8 + (lane & 3) * 2;
                __half2 bh = *(const __half2*)(g_bh + (size_t)r * SS + c);
                float2 bb = __half22float2(bh);
                float v0 = acc[mt * 8 + nt][h * 2 + 0] + bb.x;
                float v1 = acc[mt * 8 + nt][h * 2 + 1] + bb.y;
                float s0 = fast_sigmoid(v0);
                float s1 = fast_sigmoid(v1);
                *(uint32_t*)(g_P + ((size_t)bz * SS + r) * SS + c) = pack_h2(s0, s1);
            }
}

// ---------------------------------------------------------------------------
// PV: out = P @ V  (A = P[S,S] fp16, B = Vt[D,S] fp16), fp32 out. 2 CTAs/SM.
// ---------------------------------------------------------------------------
__global__ void __launch_bounds__(NCT, 2)
pv_mma(float* __restrict__ out)
{
    extern __shared__ char smem[];
    uint32_t sbase = smem_u32(smem);
    const int bz = blockIdx.z;
    const int mrow = blockIdx.y * 128;
    const int ncol = blockIdx.x * 128;

    const __half* A = g_P  + ((size_t)bz * SS + mrow) * SS;
    const __half* B = g_Vt + ((size_t)bz * DD + ncol) * SS;

    float acc[32][4];
    gemm_core<SS / 64>(A, SS, B, SS, sbase, acc);

    const int lane = threadIdx.x & 31, wid = threadIdx.x >> 5;
    const int warpM = wid & 1, warpN = wid >> 1;

#pragma unroll
    for (int mt = 0; mt < 4; ++mt)
#pragma unroll
        for (int nt = 0; nt < 8; ++nt)
#pragma unroll
            for (int h = 0; h < 2; ++h) {
                int r = mrow + warpM * 64 + mt * 16 + (lane >> 2) + h * 8;
                int c = ncol + warpN * 64 + nt * 8 + (lane & 3) * 2;
                *(float2*)(out + ((size_t)bz * SS + r) * DD + c) =
                    make_float2(acc[mt * 8 + nt][h * 2 + 0], acc[mt * 8 + nt][h * 2 + 1]);
            }
}

// ---------------------------------------------------------------------------
extern "C" void kernel_launch(void* const* d_in, const int* in_sizes, int n_in,
                              void* d_out, int out_size)
{
    const float* x    = (const float*)d_in[0];
    const float* bias = (const float*)d_in[1];
    const float* Wq   = (const float*)d_in[2];
    const float* bq   = (const float*)d_in[3];
    const float* Wk   = (const float*)d_in[4];
    const float* bk   = (const float*)d_in[5];
    const float* Wv   = (const float*)d_in[6];
    const float* bv   = (const float*)d_in[7];
    float* out = (float*)d_out;

    cudaFuncSetAttribute(qkv_mma,    cudaFuncAttributeMaxDynamicSharedMemorySize, SMEM_GEMM);
    cudaFuncSetAttribute(scores_mma, cudaFuncAttributeMaxDynamicSharedMemorySize, SMEM_GEMM);
    cudaFuncSetAttribute(pv_mma,     cudaFuncAttributeMaxDynamicSharedMemorySize, SMEM_GEMM);

    // 0) convert all fp32 inputs (x, W, bias) to fp16 in one launch
    {
        int total = NX4 + 3 * NW4 + NB4;
        cvt_all<<<(total + 255) / 256, 256>>>(x, Wq, Wk, Wv, bias);
    }

    // 1) QKV projections (V transposed in-epilogue): grid (4, 128, 3)
    qkv_mma<<<dim3(DD / 128, M_TOTAL / 128, 3), NCT, SMEM_GEMM>>>(bq, bk, bv);

    // 2) sigmoid scores (fp16 bias): grid (128, 32)  [x = ncol*4 + b]
    scores_mma<<<dim3((SS / 128) * BB, SS / 128), NCT, SMEM_GEMM>>>();

    // 3) out = P @ V: grid (4, 32, 4)
    pv_mma<<<dim3(DD / 128, SS / 128, BB), NCT, SMEM_GEMM>>>(out);
}

// round 16
// speedup vs baseline: 1.2610x; 1.2610x over previous
#include <cuda_runtime.h>
#include <cuda_fp16.h>
#include <stdint.h>
#include <math.h>

// ---------------------------------------------------------------------------
// Problem constants
// ---------------------------------------------------------------------------
#define BB 4
#define SS 4096
#define DD 512
#define M_TOTAL (BB * SS)   // 16384
#define INV_SQRT_D 0.04419417382415922f

// ---------------------------------------------------------------------------
// Scratch (__device__ globals; allocation-free rule)
// ---------------------------------------------------------------------------
__device__ __align__(256) __half g_xh[(size_t)M_TOTAL * DD];
__device__ __align__(256) __half g_Wh[(size_t)3 * DD * DD];
__device__ __align__(256) __half g_Qh[(size_t)M_TOTAL * DD];     // pre-scaled by 1/sqrt(D)
__device__ __align__(256) __half g_Kh[(size_t)M_TOTAL * DD];
__device__ __align__(256) __half g_Vt[(size_t)BB * DD * SS];     // V^T [b][d][s]
__device__ __align__(256) __half g_P [(size_t)BB * SS * SS];     // sigmoid weights

// ---------------------------------------------------------------------------
// Helpers
// ---------------------------------------------------------------------------
__device__ __forceinline__ uint32_t smem_u32(const void* p) {
    uint32_t a;
    asm("{ .reg .u64 t; cvta.to.shared.u64 t, %1; cvt.u32.u64 %0, t; }" : "=r"(a) : "l"(p));
    return a;
}

#define CP_ASYNC16(dst, src) \
    asm volatile("cp.async.cg.shared.global [%0], [%1], 16;" :: "r"(dst), "l"(src))
#define CP_COMMIT() asm volatile("cp.async.commit_group;")
#define CP_WAIT1()  asm volatile("cp.async.wait_group 1;" ::: "memory")
#define CP_WAIT0()  asm volatile("cp.async.wait_group 0;" ::: "memory")

__device__ __forceinline__ void ldsm4(uint32_t (&r)[4], uint32_t addr) {
    asm volatile("ldmatrix.sync.aligned.m8n8.x4.shared.b16 {%0,%1,%2,%3}, [%4];"
                 : "=r"(r[0]), "=r"(r[1]), "=r"(r[2]), "=r"(r[3]) : "r"(addr));
}

__device__ __forceinline__ void mma16816h(float (&d)[4], const uint32_t (&a)[4],
                                          uint32_t b0, uint32_t b1) {
    asm volatile(
        "mma.sync.aligned.m16n8k16.row.col.f32.f16.f16.f32 "
        "{%0,%1,%2,%3}, {%4,%5,%6,%7}, {%8,%9}, {%0,%1,%2,%3};"
        : "+f"(d[0]), "+f"(d[1]), "+f"(d[2]), "+f"(d[3])
        : "r"(a[0]), "r"(a[1]), "r"(a[2]), "r"(a[3]), "r"(b0), "r"(b1));
}

__device__ __forceinline__ uint32_t pack_h2(float a, float b) {
    __half2 h = __floats2half2_rn(a, b);
    return *(uint32_t*)&h;
}

// sigmoid(x) = 0.5*tanh(0.5x) + 0.5 — one MUFU op (tanh.approx) + one FMA.
__device__ __forceinline__ float fast_sigmoid(float x) {
    float t;
    asm("tanh.approx.f32 %0, %1;" : "=f"(t) : "f"(x * 0.5f));
    return fmaf(0.5f, t, 0.5f);
}

// ===========================================================================
// Unified fp16 GEMM core: 128 threads = 4 warps (2M x 2N of 64x64 warp
// tiles), CTA tile 128(M) x 128(N), BK=64, 3-stage cp.async (32KB/stage,
// 96KB total) -> 2 CTAs/SM.
// NT GEMM: A[M,K] row-major fp16, B[N,K] row-major fp16.
// 128B rows, XOR swizzle: chunk ^= (row & 7).
// ===========================================================================
#define NCT 128
#define STAGE_BYTES 32768
#define SMEM_GEMM (3 * STAGE_BYTES)    // 96 KB

__device__ __forceinline__ void load_stage(
    uint32_t sb, const __half* A, int lda, const __half* B, int ldb, int k0, int tid)
{
#pragma unroll
    for (int it = 0; it < 8; ++it) {     // A: 128 rows * 8 chunks = 1024
        int u = it * NCT + tid;
        int row = u >> 3;
        int ch = u & 7;
        uint32_t soff = (uint32_t)row * 128 + ((uint32_t)(ch ^ (row & 7)) << 4);
        CP_ASYNC16(sb + soff, (const char*)(A + (size_t)row * lda + k0) + ch * 16);
    }
#pragma unroll
    for (int it = 0; it < 8; ++it) {     // B: 128 rows * 8 chunks = 1024
        int u = it * NCT + tid;
        int row = u >> 3;
        int ch = u & 7;
        uint32_t soff = (uint32_t)row * 128 + ((uint32_t)(ch ^ (row & 7)) << 4);
        CP_ASYNC16(sb + 16384 + soff, (const char*)(B + (size_t)row * ldb + k0) + ch * 16);
    }
}

template<int KTILES>
__device__ __forceinline__ void gemm_core(
    const __half* __restrict__ A, int lda,
    const __half* __restrict__ B, int ldb,
    uint32_t sbase, float (&acc)[32][4])
{
    const int tid  = threadIdx.x;
    const int lane = tid & 31;
    const int wid  = tid >> 5;
    const int warpM = wid & 1;    // 0..1 -> 64 rows each
    const int warpN = wid >> 1;   // 0..1 -> 64 cols each

#pragma unroll
    for (int i = 0; i < 32; ++i)
#pragma unroll
        for (int j = 0; j < 4; ++j) acc[i][j] = 0.0f;

    load_stage(sbase, A, lda, B, ldb, 0, tid);
    CP_COMMIT();
    if (KTILES > 1) {
        load_stage(sbase + STAGE_BYTES, A, lda, B, ldb, 64, tid);
        CP_COMMIT();
    }

    const int arow_base = warpM * 64 + (lane & 15);
    const int a_kh = lane >> 4;
    const int brow = warpN * 64 + ((lane >> 4) << 3) + (lane & 7);
    const int b_kh = (lane >> 3) & 1;

#pragma unroll 1
    for (int kt = 0; kt < KTILES; ++kt) {
        if (kt + 1 < KTILES) { CP_WAIT1(); } else { CP_WAIT0(); }
        __syncthreads();
        if (kt + 2 < KTILES) {
            load_stage(sbase + (uint32_t)((kt + 2) % 3) * STAGE_BYTES,
                       A, lda, B, ldb, (kt + 2) * 64, tid);
            CP_COMMIT();
        }

        uint32_t sb = sbase + (uint32_t)(kt % 3) * STAGE_BYTES;
#pragma unroll
        for (int ks = 0; ks < 4; ++ks) {
            uint32_t a[4][4], b[4][4];
#pragma unroll
            for (int mt = 0; mt < 4; ++mt) {
                int r = arow_base + mt * 16;
                uint32_t ch = (uint32_t)(ks * 2 + a_kh) ^ (uint32_t)(r & 7);
                ldsm4(a[mt], sb + (uint32_t)r * 128 + ch * 16);
            }
#pragma unroll
            for (int nb = 0; nb < 4; ++nb) {
                int r = brow + nb * 16;
                uint32_t ch = (uint32_t)(ks * 2 + b_kh) ^ (uint32_t)(r & 7);
                ldsm4(b[nb], sb + 16384 + (uint32_t)r * 128 + ch * 16);
            }
#pragma unroll
            for (int mt = 0; mt < 4; ++mt)
#pragma unroll
                for (int nt = 0; nt < 8; ++nt)
                    mma16816h(acc[mt * 8 + nt], a[mt],
                              b[nt >> 1][(nt & 1) * 2], b[nt >> 1][(nt & 1) * 2 + 1]);
        }
    }
}

// ---------------------------------------------------------------------------
// Merged convert: x and Wq/Wk/Wv fp32 -> fp16, one launch.
// ---------------------------------------------------------------------------
#define NX4 (M_TOTAL * DD / 4)
#define NW4 (DD * DD / 4)

__global__ void __launch_bounds__(256)
cvt_all(const float* __restrict__ x,
        const float* __restrict__ Wq, const float* __restrict__ Wk,
        const float* __restrict__ Wv)
{
    int i = blockIdx.x * 256 + threadIdx.x;
    const float* src;
    __half* dst;
    int j;
    if (i < NX4) {
        src = x; dst = g_xh; j = i;
    } else {
        int w = i - NX4;
        if (w >= 3 * NW4) return;
        int z = w / NW4;
        j = w - z * NW4;
        src = (z == 0) ? Wq : ((z == 1) ? Wk : Wv);
        dst = g_Wh + (size_t)z * DD * DD;
    }
    float4 v = *(const float4*)(src + (size_t)j * 4);
    *(uint2*)(dst + (size_t)j * 4) = make_uint2(pack_h2(v.x, v.y), pack_h2(v.z, v.w));
}

// ---------------------------------------------------------------------------
// QKV projection: C = x @ W^T + b, grid.z selects (Q,K,V). 2 CTAs/SM.
// z==2 (V) epilogue transposes the tile in smem and writes g_Vt directly.
// ---------------------------------------------------------------------------
#define TP 130   // transpose smem pitch in halves

__global__ void __launch_bounds__(NCT, 2)
qkv_mma(const float* __restrict__ bq, const float* __restrict__ bk,
        const float* __restrict__ bv)
{
    extern __shared__ char smem[];
    uint32_t sbase = smem_u32(smem);
    const int z = blockIdx.z;
    const int mrow = blockIdx.y * 128;
    const int ncol = blockIdx.x * 128;
    const int tid = threadIdx.x;

    const __half* A = g_xh + (size_t)mrow * DD;
    const __half* B = g_Wh + (size_t)z * DD * DD + (size_t)ncol * DD;

    float acc[32][4];
    gemm_core<DD / 64>(A, DD, B, DD, sbase, acc);

    const float* bvec = (z == 0) ? bq : ((z == 1) ? bk : bv);
    const int lane = tid & 31, wid = tid >> 5;
    const int warpM = wid & 1, warpN = wid >> 1;

    if (z != 2) {
#pragma unroll
        for (int mt = 0; mt < 4; ++mt)
#pragma unroll
            for (int nt = 0; nt < 8; ++nt)
#pragma unroll
                for (int h = 0; h < 2; ++h) {
                    int r = mrow + warpM * 64 + mt * 16 + (lane >> 2) + h * 8;
                    int c = ncol + warpN * 64 + nt * 8 + (lane & 3) * 2;
                    float v0 = acc[mt * 8 + nt][h * 2 + 0] + bvec[c];
                    float v1 = acc[mt * 8 + nt][h * 2 + 1] + bvec[c + 1];
                    size_t o = (size_t)r * DD + c;
                    if (z == 0) {
                        *(uint32_t*)(g_Qh + o) = pack_h2(v0 * INV_SQRT_D, v1 * INV_SQRT_D);
                    } else {
                        *(uint32_t*)(g_Kh + o) = pack_h2(v0, v1);
                    }
                }
    } else {
        // V: transpose tile in smem (reuse pipeline stages), write g_Vt rows.
        __syncthreads();
        __half* tsm = (__half*)smem;
#pragma unroll
        for (int mt = 0; mt < 4; ++mt)
#pragma unroll
            for (int nt = 0; nt < 8; ++nt)
#pragma unroll
                for (int h = 0; h < 2; ++h) {
                    int rl = warpM * 64 + mt * 16 + (lane >> 2) + h * 8;   // s-local
                    int cl = warpN * 64 + nt * 8 + (lane & 3) * 2;        // d-local
                    float v0 = acc[mt * 8 + nt][h * 2 + 0] + bvec[ncol + cl];
                    float v1 = acc[mt * 8 + nt][h * 2 + 1] + bvec[ncol + cl + 1];
                    tsm[(cl)     * TP + rl] = __float2half_rn(v0);
                    tsm[(cl + 1) * TP + rl] = __float2half_rn(v1);
                }
        __syncthreads();

        const int bz = mrow / SS;
        const int s0 = mrow % SS;
        const __half* src = tsm + (size_t)tid * TP;
        __half* dst = g_Vt + ((size_t)bz * DD + (ncol + tid)) * SS + s0;
#pragma unroll
        for (int i = 0; i < 16; ++i) {
            uint32_t u0 = *(const uint32_t*)(src + i * 8 + 0);
            uint32_t u1 = *(const uint32_t*)(src + i * 8 + 2);
            uint32_t u2 = *(const uint32_t*)(src + i * 8 + 4);
            uint32_t u3 = *(const uint32_t*)(src + i * 8 + 6);
            *(uint4*)(dst + i * 8) = make_uint4(u0, u1, u2, u3);
        }
    }
}

// ---------------------------------------------------------------------------
// Scores: P = sigmoid(Q K^T + bias), Q pre-scaled, fp32 bias (L2-warm input).
// fp16 out. 2 CTAs/SM. grid.x = (ncol_tiles) * (b), b fastest -> bias L2-shared.
// ---------------------------------------------------------------------------
__global__ void __launch_bounds__(NCT, 2)
scores_mma(const float* __restrict__ bias)
{
    extern __shared__ char smem[];
    uint32_t sbase = smem_u32(smem);
    const int bz = blockIdx.x & 3;
    const int ncol = (blockIdx.x >> 2) * 128;
    const int mrow = blockIdx.y * 128;

    const __half* A = g_Qh + ((size_t)bz * SS + mrow) * DD;
    const __half* B = g_Kh + ((size_t)bz * SS + ncol) * DD;

    float acc[32][4];
    gemm_core<DD / 64>(A, DD, B, DD, sbase, acc);

    const int lane = threadIdx.x & 31, wid = threadIdx.x >> 5;
    const int warpM = wid & 1, warpN = wid >> 1;

#pragma unroll
    for (int mt = 0; mt < 4; ++mt)
#pragma unroll
        for (int nt = 0; nt < 8; ++nt)
#pragma unroll
            for (int h = 0; h < 2; ++h) {
                int r = mrow + warpM * 64 + mt * 16 + (lane >> 2) + h * 8;
                int c = ncol + warpN * 64 + nt * 8 + (lane & 3) * 2;
                float2 bb = *(const float2*)(bias + (size_t)r * SS + c);
                float v0 = acc[mt * 8 + nt][h * 2 + 0] + bb.x;
                float v1 = acc[mt * 8 + nt][h * 2 + 1] + bb.y;
                float s0 = fast_sigmoid(v0);
                float s1 = fast_sigmoid(v1);
                *(uint32_t*)(g_P + ((size_t)bz * SS + r) * SS + c) = pack_h2(s0, s1);
            }
}

// ---------------------------------------------------------------------------
// PV: out = P @ V  (A = P[S,S] fp16, B = Vt[D,S] fp16), fp32 out. 2 CTAs/SM.
// ---------------------------------------------------------------------------
__global__ void __launch_bounds__(NCT, 2)
pv_mma(float* __restrict__ out)
{
    extern __shared__ char smem[];
    uint32_t sbase = smem_u32(smem);
    const int bz = blockIdx.z;
    const int mrow = blockIdx.y * 128;
    const int ncol = blockIdx.x * 128;

    const __half* A = g_P  + ((size_t)bz * SS + mrow) * SS;
    const __half* B = g_Vt + ((size_t)bz * DD + ncol) * SS;

    float acc[32][4];
    gemm_core<SS / 64>(A, SS, B, SS, sbase, acc);

    const int lane = threadIdx.x & 31, wid = threadIdx.x >> 5;
    const int warpM = wid & 1, warpN = wid >> 1;

#pragma unroll
    for (int mt = 0; mt < 4; ++mt)
#pragma unroll
        for (int nt = 0; nt < 8; ++nt)
#pragma unroll
            for (int h = 0; h < 2; ++h) {
                int r = mrow + warpM * 64 + mt * 16 + (lane >> 2) + h * 8;
                int c = ncol + warpN * 64 + nt * 8 + (lane & 3) * 2;
                *(float2*)(out + ((size_t)bz * SS + r) * DD + c) =
                    make_float2(acc[mt * 8 + nt][h * 2 + 0], acc[mt * 8 + nt][h * 2 + 1]);
            }
}

// ---------------------------------------------------------------------------
extern "C" void kernel_launch(void* const* d_in, const int* in_sizes, int n_in,
                              void* d_out, int out_size)
{
    const float* x    = (const float*)d_in[0];
    const float* bias = (const float*)d_in[1];
    const float* Wq   = (const float*)d_in[2];
    const float* bq   = (const float*)d_in[3];
    const float* Wk   = (const float*)d_in[4];
    const float* bk   = (const float*)d_in[5];
    const float* Wv   = (const float*)d_in[6];
    const float* bv   = (const float*)d_in[7];
    float* out = (float*)d_out;

    cudaFuncSetAttribute(qkv_mma,    cudaFuncAttributeMaxDynamicSharedMemorySize, SMEM_GEMM);
    cudaFuncSetAttribute(scores_mma, cudaFuncAttributeMaxDynamicSharedMemorySize, SMEM_GEMM);
    cudaFuncSetAttribute(pv_mma,     cudaFuncAttributeMaxDynamicSharedMemorySize, SMEM_GEMM);

    // 0) convert all fp32 inputs to fp16 in one launch
    {
        int total = NX4 + 3 * NW4;
        cvt_all<<<(total + 255) / 256, 256>>>(x, Wq, Wk, Wv);
    }

    // 1) QKV projections (V transposed in-epilogue): grid (4, 128, 3)
    qkv_mma<<<dim3(DD / 128, M_TOTAL / 128, 3), NCT, SMEM_GEMM>>>(bq, bk, bv);

    // 2) sigmoid scores: grid (128, 32)  [x = ncol*4 + b]
    scores_mma<<<dim3((SS / 128) * BB, SS / 128), NCT, SMEM_GEMM>>>(bias);

    // 3) out = P @ V: grid (4, 32, 4)
    pv_mma<<<dim3(DD / 128, SS / 128, BB), NCT, SMEM_GEMM>>>(out);
}

// round 17
// speedup vs baseline: 1.2937x; 1.0260x over previous
#include <cuda_runtime.h>
#include <cuda_fp16.h>
#include <stdint.h>
#include <math.h>

// ---------------------------------------------------------------------------
// Problem constants
// ---------------------------------------------------------------------------
#define BB 4
#define SS 4096
#define DD 512
#define M_TOTAL (BB * SS)   // 16384
#define INV_SQRT_D 0.04419417382415922f

// ---------------------------------------------------------------------------
// Scratch (__device__ globals; allocation-free rule)
// ---------------------------------------------------------------------------
__device__ __align__(256) __half g_xh[(size_t)M_TOTAL * DD];
__device__ __align__(256) __half g_Wh[(size_t)3 * DD * DD];
__device__ __align__(256) __half g_Qh[(size_t)M_TOTAL * DD];     // pre-scaled by 1/sqrt(D)
__device__ __align__(256) __half g_Kh[(size_t)M_TOTAL * DD];
__device__ __align__(256) __half g_Vt[(size_t)BB * DD * SS];     // V^T [b][d][s]
__device__ __align__(256) __half g_P [(size_t)BB * SS * SS];     // sigmoid weights

// ---------------------------------------------------------------------------
// Helpers
// ---------------------------------------------------------------------------
__device__ __forceinline__ uint32_t smem_u32(const void* p) {
    uint32_t a;
    asm("{ .reg .u64 t; cvta.to.shared.u64 t, %1; cvt.u32.u64 %0, t; }" : "=r"(a) : "l"(p));
    return a;
}

#define CP_ASYNC16(dst, src) \
    asm volatile("cp.async.cg.shared.global [%0], [%1], 16;" :: "r"(dst), "l"(src))
#define CP_COMMIT() asm volatile("cp.async.commit_group;")
#define CP_WAIT1()  asm volatile("cp.async.wait_group 1;" ::: "memory")
#define CP_WAIT0()  asm volatile("cp.async.wait_group 0;" ::: "memory")

__device__ __forceinline__ void ldsm4(uint32_t (&r)[4], uint32_t addr) {
    asm volatile("ldmatrix.sync.aligned.m8n8.x4.shared.b16 {%0,%1,%2,%3}, [%4];"
                 : "=r"(r[0]), "=r"(r[1]), "=r"(r[2]), "=r"(r[3]) : "r"(addr));
}

__device__ __forceinline__ void mma16816h(float (&d)[4], const uint32_t (&a)[4],
                                          uint32_t b0, uint32_t b1) {
    asm volatile(
        "mma.sync.aligned.m16n8k16.row.col.f32.f16.f16.f32 "
        "{%0,%1,%2,%3}, {%4,%5,%6,%7}, {%8,%9}, {%0,%1,%2,%3};"
        : "+f"(d[0]), "+f"(d[1]), "+f"(d[2]), "+f"(d[3])
        : "r"(a[0]), "r"(a[1]), "r"(a[2]), "r"(a[3]), "r"(b0), "r"(b1));
}

__device__ __forceinline__ uint32_t pack_h2(float a, float b) {
    __half2 h = __floats2half2_rn(a, b);
    return *(uint32_t*)&h;
}

// sigmoid(x) = 0.5*tanh(0.5x) + 0.5 — one MUFU op (tanh.approx) + one FMA.
__device__ __forceinline__ float fast_sigmoid(float x) {
    float t;
    asm("tanh.approx.f32 %0, %1;" : "=f"(t) : "f"(x * 0.5f));
    return fmaf(0.5f, t, 0.5f);
}

// ===========================================================================
// Unified fp16 GEMM core: 128 threads = 4 warps (2M x 2N of 64x64 warp
// tiles), CTA tile 128(M) x 128(N), BK=64, 3-stage cp.async (32KB/stage,
// 96KB total) -> 2 CTAs/SM.
// NT GEMM: A[M,K] row-major fp16, B[N,K] row-major fp16.
// 128B rows, XOR swizzle: chunk ^= (row & 7).
// ===========================================================================
#define NCT 128
#define STAGE_BYTES 32768
#define SMEM_GEMM (3 * STAGE_BYTES)    // 96 KB

__device__ __forceinline__ void load_stage(
    uint32_t sb, const __half* A, int lda, const __half* B, int ldb, int k0, int tid)
{
#pragma unroll
    for (int it = 0; it < 8; ++it) {     // A: 128 rows * 8 chunks = 1024
        int u = it * NCT + tid;
        int row = u >> 3;
        int ch = u & 7;
        uint32_t soff = (uint32_t)row * 128 + ((uint32_t)(ch ^ (row & 7)) << 4);
        CP_ASYNC16(sb + soff, (const char*)(A + (size_t)row * lda + k0) + ch * 16);
    }
#pragma unroll
    for (int it = 0; it < 8; ++it) {     // B: 128 rows * 8 chunks = 1024
        int u = it * NCT + tid;
        int row = u >> 3;
        int ch = u & 7;
        uint32_t soff = (uint32_t)row * 128 + ((uint32_t)(ch ^ (row & 7)) << 4);
        CP_ASYNC16(sb + 16384 + soff, (const char*)(B + (size_t)row * ldb + k0) + ch * 16);
    }
}

template<int KTILES>
__device__ __forceinline__ void gemm_core(
    const __half* __restrict__ A, int lda,
    const __half* __restrict__ B, int ldb,
    uint32_t sbase, float (&acc)[32][4])
{
    const int tid  = threadIdx.x;
    const int lane = tid & 31;
    const int wid  = tid >> 5;
    const int warpM = wid & 1;    // 0..1 -> 64 rows each
    const int warpN = wid >> 1;   // 0..1 -> 64 cols each

#pragma unroll
    for (int i = 0; i < 32; ++i)
#pragma unroll
        for (int j = 0; j < 4; ++j) acc[i][j] = 0.0f;

    load_stage(sbase, A, lda, B, ldb, 0, tid);
    CP_COMMIT();
    if (KTILES > 1) {
        load_stage(sbase + STAGE_BYTES, A, lda, B, ldb, 64, tid);
        CP_COMMIT();
    }

    const int arow_base = warpM * 64 + (lane & 15);
    const int a_kh = lane >> 4;
    const int brow = warpN * 64 + ((lane >> 4) << 3) + (lane & 7);
    const int b_kh = (lane >> 3) & 1;

#pragma unroll 1
    for (int kt = 0; kt < KTILES; ++kt) {
        if (kt + 1 < KTILES) { CP_WAIT1(); } else { CP_WAIT0(); }
        __syncthreads();
        if (kt + 2 < KTILES) {
            load_stage(sbase + (uint32_t)((kt + 2) % 3) * STAGE_BYTES,
                       A, lda, B, ldb, (kt + 2) * 64, tid);
            CP_COMMIT();
        }

        uint32_t sb = sbase + (uint32_t)(kt % 3) * STAGE_BYTES;
#pragma unroll
        for (int ks = 0; ks < 4; ++ks) {
            uint32_t a[4][4], b[4][4];
#pragma unroll
            for (int mt = 0; mt < 4; ++mt) {
                int r = arow_base + mt * 16;
                uint32_t ch = (uint32_t)(ks * 2 + a_kh) ^ (uint32_t)(r & 7);
                ldsm4(a[mt], sb + (uint32_t)r * 128 + ch * 16);
            }
#pragma unroll
            for (int nb = 0; nb < 4; ++nb) {
                int r = brow + nb * 16;
                uint32_t ch = (uint32_t)(ks * 2 + b_kh) ^ (uint32_t)(r & 7);
                ldsm4(b[nb], sb + 16384 + (uint32_t)r * 128 + ch * 16);
            }
#pragma unroll
            for (int mt = 0; mt < 4; ++mt)
#pragma unroll
                for (int nt = 0; nt < 8; ++nt)
                    mma16816h(acc[mt * 8 + nt], a[mt],
                              b[nt >> 1][(nt & 1) * 2], b[nt >> 1][(nt & 1) * 2 + 1]);
        }
    }
}

// ---------------------------------------------------------------------------
// Merged convert: x and Wq/Wk/Wv fp32 -> fp16, one launch.
// ---------------------------------------------------------------------------
#define NX4 (M_TOTAL * DD / 4)
#define NW4 (DD * DD / 4)

__global__ void __launch_bounds__(256)
cvt_all(const float* __restrict__ x,
        const float* __restrict__ Wq, const float* __restrict__ Wk,
        const float* __restrict__ Wv)
{
    int i = blockIdx.x * 256 + threadIdx.x;
    const float* src;
    __half* dst;
    int j;
    if (i < NX4) {
        src = x; dst = g_xh; j = i;
    } else {
        int w = i - NX4;
        if (w >= 3 * NW4) return;
        int z = w / NW4;
        j = w - z * NW4;
        src = (z == 0) ? Wq : ((z == 1) ? Wk : Wv);
        dst = g_Wh + (size_t)z * DD * DD;
    }
    float4 v = *(const float4*)(src + (size_t)j * 4);
    *(uint2*)(dst + (size_t)j * 4) = make_uint2(pack_h2(v.x, v.y), pack_h2(v.z, v.w));
}

// ---------------------------------------------------------------------------
// QKV projection: C = x @ W^T + b, grid.z selects (Q,K,V). 2 CTAs/SM.
// z==2 (V) epilogue transposes the tile in smem and writes g_Vt directly.
// ---------------------------------------------------------------------------
#define TP 130   // transpose smem pitch in halves

__global__ void __launch_bounds__(NCT, 2)
qkv_mma(const float* __restrict__ bq, const float* __restrict__ bk,
        const float* __restrict__ bv)
{
    extern __shared__ char smem[];
    uint32_t sbase = smem_u32(smem);
    const int z = blockIdx.z;
    const int mrow = blockIdx.y * 128;
    const int ncol = blockIdx.x * 128;
    const int tid = threadIdx.x;

    const __half* A = g_xh + (size_t)mrow * DD;
    const __half* B = g_Wh + (size_t)z * DD * DD + (size_t)ncol * DD;

    float acc[32][4];
    gemm_core<DD / 64>(A, DD, B, DD, sbase, acc);

    const float* bvec = (z == 0) ? bq : ((z == 1) ? bk : bv);
    const int lane = tid & 31, wid = tid >> 5;
    const int warpM = wid & 1, warpN = wid >> 1;

    if (z != 2) {
#pragma unroll
        for (int mt = 0; mt < 4; ++mt)
#pragma unroll
            for (int nt = 0; nt < 8; ++nt)
#pragma unroll
                for (int h = 0; h < 2; ++h) {
                    int r = mrow + warpM * 64 + mt * 16 + (lane >> 2) + h * 8;
                    int c = ncol + warpN * 64 + nt * 8 + (lane & 3) * 2;
                    float v0 = acc[mt * 8 + nt][h * 2 + 0] + bvec[c];
                    float v1 = acc[mt * 8 + nt][h * 2 + 1] + bvec[c + 1];
                    size_t o = (size_t)r * DD + c;
                    if (z == 0) {
                        *(uint32_t*)(g_Qh + o) = pack_h2(v0 * INV_SQRT_D, v1 * INV_SQRT_D);
                    } else {
                        *(uint32_t*)(g_Kh + o) = pack_h2(v0, v1);
                    }
                }
    } else {
        // V: transpose tile in smem (reuse pipeline stages), write g_Vt rows.
        __syncthreads();
        __half* tsm = (__half*)smem;
#pragma unroll
        for (int mt = 0; mt < 4; ++mt)
#pragma unroll
            for (int nt = 0; nt < 8; ++nt)
#pragma unroll
                for (int h = 0; h < 2; ++h) {
                    int rl = warpM * 64 + mt * 16 + (lane >> 2) + h * 8;   // s-local
                    int cl = warpN * 64 + nt * 8 + (lane & 3) * 2;        // d-local
                    float v0 = acc[mt * 8 + nt][h * 2 + 0] + bvec[ncol + cl];
                    float v1 = acc[mt * 8 + nt][h * 2 + 1] + bvec[ncol + cl + 1];
                    tsm[(cl)     * TP + rl] = __float2half_rn(v0);
                    tsm[(cl + 1) * TP + rl] = __float2half_rn(v1);
                }
        __syncthreads();

        const int bz = mrow / SS;
        const int s0 = mrow % SS;
        const __half* src = tsm + (size_t)tid * TP;
        __half* dst = g_Vt + ((size_t)bz * DD + (ncol + tid)) * SS + s0;
#pragma unroll
        for (int i = 0; i < 16; ++i) {
            uint32_t u0 = *(const uint32_t*)(src + i * 8 + 0);
            uint32_t u1 = *(const uint32_t*)(src + i * 8 + 2);
            uint32_t u2 = *(const uint32_t*)(src + i * 8 + 4);
            uint32_t u3 = *(const uint32_t*)(src + i * 8 + 6);
            *(uint4*)(dst + i * 8) = make_uint4(u0, u1, u2, u3);
        }
    }
}

// ---------------------------------------------------------------------------
// Scores: P = sigmoid(Q K^T + bias), Q pre-scaled, fp32 bias. fp16 out.
// 2 CTAs/SM. grid.x = (ncol_tiles) * (b), b fastest -> bias L2-shared.
// Specialized mainloop (KTILES=8): the last two k-tiles' freed pipeline
// stages receive the fp32 bias tile via cp.async (rows 0-63 -> stage 2 at
// kt=6, rows 64-127 -> stage 0 at kt=7), fully overlapped with MMA. The
// epilogue then reads bias from smem instead of issuing cold LDGs.
// Commit order (...tile6, tile7, biasP1, biasP2) + in-order group completion
// means wait_group(1) at kt=6/7 still certifies exactly the tile computed.
// ---------------------------------------------------------------------------
__global__ void __launch_bounds__(NCT, 2)
scores_mma(const float* __restrict__ bias)
{
    extern __shared__ char smem[];
    uint32_t sbase = smem_u32(smem);
    const int bz = blockIdx.x & 3;
    const int ncol = (blockIdx.x >> 2) * 128;
    const int mrow = blockIdx.y * 128;

    const __half* A = g_Qh + ((size_t)bz * SS + mrow) * DD;
    const __half* B = g_Kh + ((size_t)bz * SS + ncol) * DD;
    const float* bsrc = bias + (size_t)mrow * SS + ncol;

    const int tid  = threadIdx.x;
    const int lane = tid & 31;
    const int wid  = tid >> 5;
    const int warpM = wid & 1;
    const int warpN = wid >> 1;

    float acc[32][4];
#pragma unroll
    for (int i = 0; i < 32; ++i)
#pragma unroll
        for (int j = 0; j < 4; ++j) acc[i][j] = 0.0f;

    load_stage(sbase, A, DD, B, DD, 0, tid);
    CP_COMMIT();
    load_stage(sbase + STAGE_BYTES, A, DD, B, DD, 64, tid);
    CP_COMMIT();

    const int arow_base = warpM * 64 + (lane & 15);
    const int a_kh = lane >> 4;
    const int brow = warpN * 64 + ((lane >> 4) << 3) + (lane & 7);
    const int b_kh = (lane >> 3) & 1;

#pragma unroll 1
    for (int kt = 0; kt < 8; ++kt) {
        CP_WAIT1();                       // in-order groups: tile kt is ready
        __syncthreads();
        if (kt + 2 < 8) {
            load_stage(sbase + (uint32_t)((kt + 2) % 3) * STAGE_BYTES,
                       A, DD, B, DD, (kt + 2) * 64, tid);
            CP_COMMIT();
        } else {
            // bias prefetch into the freed stage: part 0 at kt=6, part 1 at kt=7
            int part = kt - 6;
            uint32_t stg = sbase + (uint32_t)((kt + 2) % 3) * STAGE_BYTES;
#pragma unroll
            for (int it = 0; it < 16; ++it) {     // 64 rows * 32 chunks of 16B
                int u = it * NCT + tid;
                int row = u >> 5;                 // 0..63
                int ch = u & 31;
                uint32_t soff = (uint32_t)row * 512 +
                                ((uint32_t)(ch ^ (row & 31)) << 4);
                CP_ASYNC16(stg + soff,
                           (const char*)(bsrc + (size_t)(part * 64 + row) * SS) + ch * 16);
            }
            CP_COMMIT();
        }

        uint32_t sb = sbase + (uint32_t)(kt % 3) * STAGE_BYTES;
#pragma unroll
        for (int ks = 0; ks < 4; ++ks) {
            uint32_t a[4][4], b[4][4];
#pragma unroll
            for (int mt = 0; mt < 4; ++mt) {
                int r = arow_base + mt * 16;
                uint32_t ch = (uint32_t)(ks * 2 + a_kh) ^ (uint32_t)(r & 7);
                ldsm4(a[mt], sb + (uint32_t)r * 128 + ch * 16);
            }
#pragma unroll
            for (int nb = 0; nb < 4; ++nb) {
                int r = brow + nb * 16;
                uint32_t ch = (uint32_t)(ks * 2 + b_kh) ^ (uint32_t)(r & 7);
                ldsm4(b[nb], sb + 16384 + (uint32_t)r * 128 + ch * 16);
            }
#pragma unroll
            for (int mt = 0; mt < 4; ++mt)
#pragma unroll
                for (int nt = 0; nt < 8; ++nt)
                    mma16816h(acc[mt * 8 + nt], a[mt],
                              b[nt >> 1][(nt & 1) * 2], b[nt >> 1][(nt & 1) * 2 + 1]);
        }
    }

    CP_WAIT0();            // bias parts complete
    __syncthreads();       // visible to all threads

    // epilogue: bias from smem. part = warpM (rows 0-63 stage2, 64-127 stage0)
    char* bstage = smem + (warpM ? 0 : 2 * STAGE_BYTES);

#pragma unroll
    for (int mt = 0; mt < 4; ++mt)
#pragma unroll
        for (int nt = 0; nt < 8; ++nt)
#pragma unroll
            for (int h = 0; h < 2; ++h) {
                int rl = warpM * 64 + mt * 16 + (lane >> 2) + h * 8;
                int row = rl & 63;
                int cl = warpN * 64 + nt * 8 + (lane & 3) * 2;
                uint32_t boff = (uint32_t)row * 512 +
                                ((uint32_t)((cl >> 2) ^ (row & 31)) << 4) +
                                (uint32_t)(cl & 3) * 4;
                float2 bb = *(const float2*)(bstage + boff);
                float v0 = acc[mt * 8 + nt][h * 2 + 0] + bb.x;
                float v1 = acc[mt * 8 + nt][h * 2 + 1] + bb.y;
                float s0 = fast_sigmoid(v0);
                float s1 = fast_sigmoid(v1);
                int r = mrow + rl;
                int c = ncol + cl;
                *(uint32_t*)(g_P + ((size_t)bz * SS + r) * SS + c) = pack_h2(s0, s1);
            }
}

// ---------------------------------------------------------------------------
// PV: out = P @ V  (A = P[S,S] fp16, B = Vt[D,S] fp16), fp32 out. 2 CTAs/SM.
// ---------------------------------------------------------------------------
__global__ void __launch_bounds__(NCT, 2)
pv_mma(float* __restrict__ out)
{
    extern __shared__ char smem[];
    uint32_t sbase = smem_u32(smem);
    const int bz = blockIdx.z;
    const int mrow = blockIdx.y * 128;
    const int ncol = blockIdx.x * 128;

    const __half* A = g_P  + ((size_t)bz * SS + mrow) * SS;
    const __half* B = g_Vt + ((size_t)bz * DD + ncol) * SS;

    float acc[32][4];
    gemm_core<SS / 64>(A, SS, B, SS, sbase, acc);

    const int lane = threadIdx.x & 31, wid = threadIdx.x >> 5;
    const int warpM = wid & 1, warpN = wid >> 1;

#pragma unroll
    for (int mt = 0; mt < 4; ++mt)
#pragma unroll
        for (int nt = 0; nt < 8; ++nt)
#pragma unroll
            for (int h = 0; h < 2; ++h) {
                int r = mrow + warpM * 64 + mt * 16 + (lane >> 2) + h * 8;
                int c = ncol + warpN * 64 + nt * 8 + (lane & 3) * 2;
                *(float2*)(out + ((size_t)bz * SS + r) * DD + c) =
                    make_float2(acc[mt * 8 + nt][h * 2 + 0], acc[mt * 8 + nt][h * 2 + 1]);
            }
}

// ---------------------------------------------------------------------------
extern "C" void kernel_launch(void* const* d_in, const int* in_sizes, int n_in,
                              void* d_out, int out_size)
{
    const float* x    = (const float*)d_in[0];
    const float* bias = (const float*)d_in[1];
    const float* Wq   = (const float*)d_in[2];
    const float* bq   = (const float*)d_in[3];
    const float* Wk   = (const float*)d_in[4];
    const float* bk   = (const float*)d_in[5];
    const float* Wv   = (const float*)d_in[6];
    const float* bv   = (const float*)d_in[7];
    float* out = (float*)d_out;

    cudaFuncSetAttribute(qkv_mma,    cudaFuncAttributeMaxDynamicSharedMemorySize, SMEM_GEMM);
    cudaFuncSetAttribute(scores_mma, cudaFuncAttributeMaxDynamicSharedMemorySize, SMEM_GEMM);
    cudaFuncSetAttribute(pv_mma,     cudaFuncAttributeMaxDynamicSharedMemorySize, SMEM_GEMM);

    // 0) convert all fp32 inputs to fp16 in one launch
    {
        int total = NX4 + 3 * NW4;
        cvt_all<<<(total + 255) / 256, 256>>>(x, Wq, Wk, Wv);
    }

    // 1) QKV projections (V transposed in-epilogue): grid (4, 128, 3)
    qkv_mma<<<dim3(DD / 128, M_TOTAL / 128, 3), NCT, SMEM_GEMM>>>(bq, bk, bv);

    // 2) sigmoid scores (bias prefetched into dying pipeline stages):
    //    grid (128, 32)  [x = ncol*4 + b]
    scores_mma<<<dim3((SS / 128) * BB, SS / 128), NCT, SMEM_GEMM>>>(bias);

    // 3) out = P @ V: grid (4, 32, 4)
    pv_mma<<<dim3(DD / 128, SS / 128, BB), NCT, SMEM_GEMM>>>(out);
}